// round 17
// baseline (speedup 1.0000x reference)
#include <cuda_runtime.h>
#include <cuda_bf16.h>
#include <cstdint>

namespace {
constexpr int GRID = 64, NTHR = 1024, ROWS = 16;
constexpr int NEVAL = 32;
constexpr int IMG1_N = 16 * 128 * 32;   // (kt, g, lane) uint4 = 1 MB
constexpr int IMG2_N = 64 * 32 * 32;    // 1 MB
constexpr uint32_t OFF_PROBE = 0;                 // f32 [16][260]
constexpr uint32_t OFF_HH    = 16640;             // bf16 [16][1032]
constexpr uint32_t OFF_HL    = OFF_HH + 33024;    // 49664
constexpr uint32_t OFF_B1    = OFF_HL + 33024;    // 82688
constexpr uint32_t OFF_STATE = OFF_B1 + 4096;     // 86784: float4 zb/ac per thread
constexpr uint32_t SMEM_SZ   = OFF_STATE + 32768; // 119552
}

__device__ __align__(16) uint4 g_img1[IMG1_N];
__device__ __align__(16) uint4 g_img2[IMG2_N];

__device__ __forceinline__ unsigned bf2pack(__nv_bfloat16 a, __nv_bfloat16 b) {
    __nv_bfloat162 t; t.x = a; t.y = b;
    return *reinterpret_cast<unsigned*>(&t);
}
__device__ __forceinline__ void split2(float x, float y, unsigned& hi, unsigned& lo) {
    const __nv_bfloat16 hx = __float2bfloat16(x), hy = __float2bfloat16(y);
    const __nv_bfloat16 lx = __float2bfloat16(x - __bfloat162float(hx));
    const __nv_bfloat16 ly = __float2bfloat16(y - __bfloat162float(hy));
    hi = bf2pack(hx, hy);
    lo = bf2pack(lx, ly);
}
__device__ __forceinline__ float tanha(float x) {
    float y; asm("tanh.approx.f32 %0, %1;" : "=f"(y) : "f"(x)); return y;
}

// ---------------- prep: identical validated layouts (R12) -------------------
__global__ void prep_kernel(const float* __restrict__ W1, const float* __restrict__ W2) {
    const int e = blockIdx.x * blockDim.x + threadIdx.x;
    if (e < IMG1_N) {
        const int l = e & 31, g = (e >> 5) & 127, kt = e >> 12;
        const int n  = g * 8 + (l >> 2);
        const int k0 = kt * 16 + 2 * (l & 3);
        unsigned h0, l0, h1, l1;
        split2(W1[k0 * 1024 + n],       W1[(k0 + 1) * 1024 + n], h0, l0);
        split2(W1[(k0 + 8) * 1024 + n], W1[(k0 + 9) * 1024 + n], h1, l1);
        g_img1[e] = make_uint4(h0, h1, l0, l1);
    } else if (e < IMG1_N + IMG2_N) {
        const int e2 = e - IMG1_N;
        const int l = e2 & 31, g = (e2 >> 5) & 31, kt = e2 >> 10;
        const int n  = g * 8 + (l >> 2);
        const int k0 = kt * 16 + 2 * (l & 3);
        unsigned h0, l0, h1, l1;
        split2(W2[k0 * 256 + n],       W2[(k0 + 1) * 256 + n], h0, l0);
        split2(W2[(k0 + 8) * 256 + n], W2[(k0 + 9) * 256 + n], h1, l1);
        g_img2[e2] = make_uint4(h0, h1, l0, l1);
    }
}

__device__ __forceinline__ void mma16(float* d, unsigned a0, unsigned a1, unsigned a2,
                                      unsigned a3, unsigned b0, unsigned b1) {
    asm volatile(
        "mma.sync.aligned.m16n8k16.row.col.f32.bf16.bf16.f32 "
        "{%0,%1,%2,%3}, {%4,%5,%6,%7}, {%8,%9}, {%0,%1,%2,%3};"
        : "+f"(d[0]), "+f"(d[1]), "+f"(d[2]), "+f"(d[3])
        : "r"(a0), "r"(a1), "r"(a2), "r"(a3), "r"(b0), "r"(b1));
}

__global__ void __launch_bounds__(NTHR, 1) node_mma_kernel(
    const float* __restrict__ z0, const float* __restrict__ tt,
    const float* __restrict__ b2, const float* __restrict__ b1,
    float* __restrict__ out)
{
    extern __shared__ __align__(16) unsigned char sm[];
    float* s_probe = reinterpret_cast<float*>(sm + OFF_PROBE);             // [16][260]
    unsigned short* s_hh = reinterpret_cast<unsigned short*>(sm + OFF_HH); // [16][1032]
    unsigned short* s_hl = reinterpret_cast<unsigned short*>(sm + OFF_HL);
    float* s_b1 = reinterpret_cast<float*>(sm + OFF_B1);
    float4* s_state = reinterpret_cast<float4*>(sm + OFF_STATE);           // [tid*2 + {0,1}]

    const int tid = threadIdx.x;
    const int warp = tid >> 5, lane = tid & 31;
    const int gr = lane >> 2, tc = lane & 3;
    const int row0 = blockIdx.x * ROWS;

    const float h  = (tt[1] - tt[0]) * 0.125f;
    const float h2 = 0.5f * h, h6 = h * (1.0f / 6.0f);

    if (tid < 256) {
        const float4 v = reinterpret_cast<const float4*>(b1)[tid];
        reinterpret_cast<float4*>(s_b1)[tid] = v;
    }

    // phase-2 / glue ownership: 1 ntile at N2 = warp*8; rows gr, gr+8; cols 2tc,2tc+1
    const int N2 = warp * 8;
    {
        const int c0 = N2 + 2 * tc;
        float4 zb;
        zb.x = z0[(row0 + gr) * 256 + c0];
        zb.y = z0[(row0 + gr) * 256 + c0 + 1];
        zb.z = z0[(row0 + gr + 8) * 256 + c0];
        zb.w = z0[(row0 + gr + 8) * 256 + c0 + 1];
        *reinterpret_cast<float2*>(&s_probe[gr * 260 + c0])       = make_float2(zb.x, zb.y);
        *reinterpret_cast<float2*>(&s_probe[(gr + 8) * 260 + c0]) = make_float2(zb.z, zb.w);
        s_state[tid * 2]     = zb;
        s_state[tid * 2 + 1] = make_float4(0.f, 0.f, 0.f, 0.f);
    }
    __syncthreads();

    const int N1 = warp * 32;                               // phase-1 N-slice base (4 ntiles)
    const uint4* img1w = g_img1 + (warp * 4) * 32 + lane;   // + kt*4096 + g*32
    const uint4* img2w = g_img2 + warp * 32 + lane;         // + kt*1024

    for (int ev = 0; ev < NEVAL; ++ev) {
        const int e = ev & 3;

        // ---------- phase 1: hid = tanh(probe @ W1 + b1), N-slice 32 ----------
        float a1c[4][4];
        #pragma unroll
        for (int nt = 0; nt < 4; ++nt)
            #pragma unroll
            for (int i = 0; i < 4; ++i) a1c[nt][i] = 0.0f;

        #pragma unroll 4
        for (int kt = 0; kt < 16; ++kt) {
            uint4 cur0 = img1w[kt * 4096];
            uint4 cur1 = img1w[kt * 4096 + 32];
            uint4 cur2 = img1w[kt * 4096 + 64];
            uint4 cur3 = img1w[kt * 4096 + 96];
            const int kb = kt * 16 + 2 * tc;
            const float2 q0 = *reinterpret_cast<const float2*>(&s_probe[gr * 260 + kb]);
            const float2 q1 = *reinterpret_cast<const float2*>(&s_probe[gr * 260 + kb + 8]);
            const float2 q2 = *reinterpret_cast<const float2*>(&s_probe[(gr + 8) * 260 + kb]);
            const float2 q3 = *reinterpret_cast<const float2*>(&s_probe[(gr + 8) * 260 + kb + 8]);
            unsigned ah0, al0, ah1, al1, ah2, al2, ah3, al3;
            split2(q0.x, q0.y, ah0, al0);
            split2(q2.x, q2.y, ah1, al1);
            split2(q1.x, q1.y, ah2, al2);
            split2(q3.x, q3.y, ah3, al3);
            mma16(a1c[0], ah0, ah1, ah2, ah3, cur0.x, cur0.y);
            mma16(a1c[0], ah0, ah1, ah2, ah3, cur0.z, cur0.w);
            mma16(a1c[0], al0, al1, al2, al3, cur0.x, cur0.y);
            mma16(a1c[1], ah0, ah1, ah2, ah3, cur1.x, cur1.y);
            mma16(a1c[1], ah0, ah1, ah2, ah3, cur1.z, cur1.w);
            mma16(a1c[1], al0, al1, al2, al3, cur1.x, cur1.y);
            mma16(a1c[2], ah0, ah1, ah2, ah3, cur2.x, cur2.y);
            mma16(a1c[2], ah0, ah1, ah2, ah3, cur2.z, cur2.w);
            mma16(a1c[2], al0, al1, al2, al3, cur2.x, cur2.y);
            mma16(a1c[3], ah0, ah1, ah2, ah3, cur3.x, cur3.y);
            mma16(a1c[3], ah0, ah1, ah2, ah3, cur3.z, cur3.w);
            mma16(a1c[3], al0, al1, al2, al3, cur3.x, cur3.y);
        }

        #pragma unroll
        for (int nt = 0; nt < 4; ++nt) {
            const int c0 = N1 + 8 * nt + 2 * tc;
            const float v0 = tanha(a1c[nt][0] + s_b1[c0]);
            const float v1 = tanha(a1c[nt][1] + s_b1[c0 + 1]);
            const float v2 = tanha(a1c[nt][2] + s_b1[c0]);
            const float v3 = tanha(a1c[nt][3] + s_b1[c0 + 1]);
            unsigned hiA, loA, hiB, loB;
            split2(v0, v1, hiA, loA);
            split2(v2, v3, hiB, loB);
            *reinterpret_cast<unsigned*>(&s_hh[gr * 1032 + c0])       = hiA;
            *reinterpret_cast<unsigned*>(&s_hl[gr * 1032 + c0])       = loA;
            *reinterpret_cast<unsigned*>(&s_hh[(gr + 8) * 1032 + c0]) = hiB;
            *reinterpret_cast<unsigned*>(&s_hl[(gr + 8) * 1032 + c0]) = loB;
        }
        __syncthreads();

        // ---------- phase 2: k = hid @ W2 + b2, 1 ntile ----------
        float a2c[4];
        #pragma unroll
        for (int i = 0; i < 4; ++i) a2c[i] = 0.0f;

        #pragma unroll 4
        for (int kt = 0; kt < 64; ++kt) {
            const uint4 wv = img2w[kt * 1024];
            const int kb = kt * 16 + 2 * tc;
            const unsigned ah0 = *reinterpret_cast<const unsigned*>(&s_hh[gr * 1032 + kb]);
            const unsigned ah1 = *reinterpret_cast<const unsigned*>(&s_hh[(gr + 8) * 1032 + kb]);
            const unsigned ah2 = *reinterpret_cast<const unsigned*>(&s_hh[gr * 1032 + kb + 8]);
            const unsigned ah3 = *reinterpret_cast<const unsigned*>(&s_hh[(gr + 8) * 1032 + kb + 8]);
            const unsigned al0 = *reinterpret_cast<const unsigned*>(&s_hl[gr * 1032 + kb]);
            const unsigned al1 = *reinterpret_cast<const unsigned*>(&s_hl[(gr + 8) * 1032 + kb]);
            const unsigned al2 = *reinterpret_cast<const unsigned*>(&s_hl[gr * 1032 + kb + 8]);
            const unsigned al3 = *reinterpret_cast<const unsigned*>(&s_hl[(gr + 8) * 1032 + kb + 8]);
            mma16(a2c, ah0, ah1, ah2, ah3, wv.x, wv.y);
            mma16(a2c, ah0, ah1, ah2, ah3, wv.z, wv.w);
            mma16(a2c, al0, al1, al2, al3, wv.x, wv.y);
        }

        // ---------- RK4 glue (state in smem) + probe rebuild ----------
        {
            const int c0 = N2 + 2 * tc;
            float4 zb = s_state[tid * 2];
            float4 ac = s_state[tid * 2 + 1];
            const float bv0 = b2[c0], bv1 = b2[c0 + 1];
            float kv[4], p[4];
            kv[0] = a2c[0] + bv0; kv[1] = a2c[1] + bv1;
            kv[2] = a2c[2] + bv0; kv[3] = a2c[3] + bv1;
            float* zbp = &zb.x;
            float* acp = &ac.x;
            #pragma unroll
            for (int i = 0; i < 4; ++i) {
                if (e == 0)      { acp[i] = kv[i];                        p[i] = fmaf(h2, kv[i], zbp[i]); }
                else if (e == 1) { acp[i] = fmaf(2.0f, kv[i], acp[i]);    p[i] = fmaf(h2, kv[i], zbp[i]); }
                else if (e == 2) { acp[i] = fmaf(2.0f, kv[i], acp[i]);    p[i] = fmaf(h, kv[i], zbp[i]); }
                else             { acp[i] += kv[i]; zbp[i] = fmaf(h6, acp[i], zbp[i]); p[i] = zbp[i]; }
            }
            *reinterpret_cast<float2*>(&s_probe[gr * 260 + c0])       = make_float2(p[0], p[1]);
            *reinterpret_cast<float2*>(&s_probe[(gr + 8) * 260 + c0]) = make_float2(p[2], p[3]);
            s_state[tid * 2]     = zb;
            s_state[tid * 2 + 1] = ac;
        }
        __syncthreads();
    }

    {
        const int c0 = N2 + 2 * tc;
        const float4 zb = s_state[tid * 2];
        out[(row0 + gr) * 256 + c0]         = zb.x;
        out[(row0 + gr) * 256 + c0 + 1]     = zb.y;
        out[(row0 + gr + 8) * 256 + c0]     = zb.z;
        out[(row0 + gr + 8) * 256 + c0 + 1] = zb.w;
    }
}

extern "C" void kernel_launch(void* const* d_in, const int* in_sizes, int n_in,
                              void* d_out, int out_size) {
    const float* z0 = (const float*)d_in[0];
    const float* tt = (const float*)d_in[1];
    const float* W1 = (const float*)d_in[2];
    const float* b1 = (const float*)d_in[3];
    const float* W2 = (const float*)d_in[4];
    const float* b2 = (const float*)d_in[5];
    float* out = (float*)d_out;
    (void)in_sizes; (void)n_in; (void)out_size;

    static bool attr_set = false;
    if (!attr_set) {
        cudaFuncSetAttribute(node_mma_kernel, cudaFuncAttributeMaxDynamicSharedMemorySize,
                             (int)SMEM_SZ);
        attr_set = true;
    }
    prep_kernel<<<(IMG1_N + IMG2_N) / 256, 256>>>(W1, W2);
    node_mma_kernel<<<GRID, NTHR, SMEM_SZ>>>(z0, tt, b2, b1, out);
}